// round 1
// baseline (speedup 1.0000x reference)
#include <cuda_runtime.h>

#define Hh 192
#define Ww 192

// Scratch (no cudaMalloc allowed)
__device__ float g_att[8 * 9 * 192 * 192];   // attention maps [b][p][y][x]
__device__ float g_pooled[8 * 32];
__device__ float g_bias[8 * 32];

// ---------------------------------------------------------------------------
// Kernel 1: global average pool. One block per (b,n).
// ---------------------------------------------------------------------------
__global__ void pooled_kernel(const float* __restrict__ x) {
    int bn = blockIdx.x;  // 0..255
    const float* p = x + (size_t)bn * Hh * Ww;
    float s = 0.f;
    for (int i = threadIdx.x; i < Hh * Ww; i += 256) s += p[i];
    __shared__ float red[256];
    red[threadIdx.x] = s;
    __syncthreads();
    for (int o = 128; o > 0; o >>= 1) {
        if (threadIdx.x < o) red[threadIdx.x] += red[threadIdx.x + o];
        __syncthreads();
    }
    if (threadIdx.x == 0) g_pooled[bn] = red[0] * (1.f / (Hh * Ww));
}

// ---------------------------------------------------------------------------
// Kernel 2: bias MLP. bias[b,m] = b2b[m] + sum_k relu(pooled@b1w^T + b1b)[b,k]*b2w[m,k]
// ---------------------------------------------------------------------------
__global__ void bias_kernel(const float* __restrict__ b1w, const float* __restrict__ b1b,
                            const float* __restrict__ b2w, const float* __restrict__ b2b) {
    __shared__ float h[8 * 32];
    int t = threadIdx.x;
    int b = t >> 5, k = t & 31;
    float s = b1b[k];
    for (int n = 0; n < 32; n++) s += g_pooled[b * 32 + n] * b1w[k * 32 + n];
    h[t] = fmaxf(s, 0.f);
    __syncthreads();
    int m = k;
    float s2 = b2b[m];
    for (int kk = 0; kk < 32; kk++) s2 += h[b * 32 + kk] * b2w[m * 32 + kk];
    g_bias[t] = s2;
}

// ---------------------------------------------------------------------------
// Kernel 3: attention stack.
// Tile 32x32 pixels, 256 threads, each thread 4 pixels strided by 8 in x,
// 9 conv outputs -> relu -> 9x9 -> relu -> 9x9 -> sigmoid.
// smem xs stride 40 => lane address 8*py + c, conflict-free.
// ---------------------------------------------------------------------------
#define AXS 40
__global__ __launch_bounds__(256, 1)
void attn_kernel(const float* __restrict__ x, const float* __restrict__ a1w,
                 const float* __restrict__ a1b, const float* __restrict__ a2w,
                 const float* __restrict__ a2b, const float* __restrict__ a3w,
                 const float* __restrict__ a3b) {
    extern __shared__ float sm[];
    float* xs = sm;                     // 32*34*40
    float* w1 = xs + 32 * 34 * AXS;     // 2592  [o][n][t]
    float* w2 = w1 + 2592;              // 81
    float* w3 = w2 + 81;                // 81
    float* bb1 = w3 + 81;               // 9
    float* bb2 = bb1 + 9;               // 9
    float* bb3 = bb2 + 9;               // 9

    int b = blockIdx.z;
    int y0 = blockIdx.y * 32, x0 = blockIdx.x * 32;
    int tid = threadIdx.x;

    for (int i = tid; i < 2592; i += 256) w1[i] = a1w[i];
    if (tid < 81) { w2[tid] = a2w[tid]; w3[tid] = a3w[tid]; }
    if (tid < 9) { bb1[tid] = a1b[tid]; bb2[tid] = a2b[tid]; bb3[tid] = a3b[tid]; }

    const float* xb = x + (size_t)b * 32 * Hh * Ww;
    for (int i = tid; i < 32 * 34 * 34; i += 256) {
        int n = i / (34 * 34);
        int r = i % (34 * 34);
        int yy = r / 34, xx = r % 34;
        int gy = y0 + yy - 1, gx = x0 + xx - 1;
        float v = 0.f;
        if ((unsigned)gy < Hh && (unsigned)gx < Ww) v = xb[(n * Hh + gy) * Ww + gx];
        xs[(n * 34 + yy) * AXS + xx] = v;
    }
    __syncthreads();

    int py = tid >> 3;      // 0..31
    int c = tid & 7;        // 0..7, pixels px = c + 8*j

    float acc[9][4];
#pragma unroll
    for (int o = 0; o < 9; o++)
#pragma unroll
        for (int j = 0; j < 4; j++) acc[o][j] = 0.f;

    for (int n = 0; n < 32; n++) {
        const float* xr = xs + (n * 34 + py) * AXS + c;
        const float* wn = w1 + n * 9;
#pragma unroll
        for (int ki = 0; ki < 3; ki++) {
#pragma unroll
            for (int kj = 0; kj < 3; kj++) {
                float v0 = xr[ki * AXS + kj];
                float v1 = xr[ki * AXS + kj + 8];
                float v2 = xr[ki * AXS + kj + 16];
                float v3 = xr[ki * AXS + kj + 24];
                int t = ki * 3 + kj;
#pragma unroll
                for (int o = 0; o < 9; o++) {
                    float w = wn[o * 288 + t];
                    acc[o][0] += w * v0;
                    acc[o][1] += w * v1;
                    acc[o][2] += w * v2;
                    acc[o][3] += w * v3;
                }
            }
        }
    }

    int gy = y0 + py;
#pragma unroll
    for (int j = 0; j < 4; j++) {
        int gx = x0 + c + 8 * j;
        float u[9], z[9];
#pragma unroll
        for (int o = 0; o < 9; o++) u[o] = fmaxf(acc[o][j] + bb1[o], 0.f);
#pragma unroll
        for (int o2 = 0; o2 < 9; o2++) {
            float s = bb2[o2];
#pragma unroll
            for (int o = 0; o < 9; o++) s += w2[o2 * 9 + o] * u[o];
            z[o2] = fmaxf(s, 0.f);
        }
#pragma unroll
        for (int o3 = 0; o3 < 9; o3++) {
            float s = bb3[o3];
#pragma unroll
            for (int o2 = 0; o2 < 9; o2++) s += w3[o3 * 9 + o2] * z[o2];
            float att = 1.f / (1.f + __expf(-s));
            g_att[((b * 9 + o3) * Hh + gy) * Ww + gx] = att;
        }
    }
}

// ---------------------------------------------------------------------------
// Kernel 4: main attention-weighted conv.
// Tile 16x16 pixels, 256 threads = 4 m-groups x 64 pixel-groups.
// Thread: 8 m values x 4 pixels (strided by 4 in x) = 32 accumulators.
// smem xs stride 20 => lane address 20*py + c, conflict-free.
// Weights relaid [p][n][m] so the 8 m weights are two float4 broadcasts.
// ---------------------------------------------------------------------------
#define MXS 20
__global__ __launch_bounds__(256, 2)
void main_kernel(const float* __restrict__ x, const float* __restrict__ weight,
                 float* __restrict__ out) {
    extern __shared__ float sm[];
    float* xs = sm;                 // 32*18*20 = 11520
    float* ws = xs + 11520;         // 9216 [p][n][m]
    float* atts = ws + 9216;        // 9*16*16 = 2304

    int b = blockIdx.z;
    int y0 = blockIdx.y * 16, x0 = blockIdx.x * 16;
    int tid = threadIdx.x;

    const float* xb = x + (size_t)b * 32 * Hh * Ww;
    for (int i = tid; i < 32 * 18 * 18; i += 256) {
        int n = i / (18 * 18);
        int r = i % (18 * 18);
        int yy = r / 18, xx = r % 18;
        int gy = y0 + yy - 1, gx = x0 + xx - 1;
        float v = 0.f;
        if ((unsigned)gy < Hh && (unsigned)gx < Ww) v = xb[(n * Hh + gy) * Ww + gx];
        xs[(n * 18 + yy) * MXS + xx] = v;
    }
    for (int i = tid; i < 9216; i += 256) {
        int p = i >> 10;
        int r = i & 1023;
        int n = r >> 5;
        int m = r & 31;
        ws[i] = weight[(m * 32 + n) * 9 + p];
    }
    for (int i = tid; i < 2304; i += 256) {
        int p = i >> 8;
        int r = i & 255;
        int yy = r >> 4, xx = r & 15;
        atts[i] = g_att[((b * 9 + p) * Hh + y0 + yy) * Ww + x0 + xx];
    }
    __syncthreads();

    int mg = tid >> 6;        // 0..3
    int pg = tid & 63;
    int m0 = mg * 8;
    int py = pg >> 2;         // 0..15
    int c = pg & 3;           // pixels px = c + 4*j

    float acc[8][4];
#pragma unroll
    for (int mm = 0; mm < 8; mm++)
#pragma unroll
        for (int j = 0; j < 4; j++) acc[mm][j] = 0.f;

#pragma unroll
    for (int p = 0; p < 9; p++) {
        int ki = p / 3, kj = p % 3;
        float a0 = atts[(p * 16 + py) * 16 + c];
        float a1 = atts[(p * 16 + py) * 16 + c + 4];
        float a2 = atts[(p * 16 + py) * 16 + c + 8];
        float a3 = atts[(p * 16 + py) * 16 + c + 12];
        const float* wp = ws + p * 1024 + m0;
        const float* xp = xs + (py + ki) * MXS + c + kj;
        for (int n = 0; n < 32; n++) {
            const float* xr = xp + n * (18 * MXS);
            float v0 = xr[0] * a0;
            float v1 = xr[4] * a1;
            float v2 = xr[8] * a2;
            float v3 = xr[12] * a3;
            const float* wr = wp + n * 32;
            float4 wa = *(const float4*)wr;
            float4 wb = *(const float4*)(wr + 4);
            acc[0][0] += wa.x * v0; acc[0][1] += wa.x * v1; acc[0][2] += wa.x * v2; acc[0][3] += wa.x * v3;
            acc[1][0] += wa.y * v0; acc[1][1] += wa.y * v1; acc[1][2] += wa.y * v2; acc[1][3] += wa.y * v3;
            acc[2][0] += wa.z * v0; acc[2][1] += wa.z * v1; acc[2][2] += wa.z * v2; acc[2][3] += wa.z * v3;
            acc[3][0] += wa.w * v0; acc[3][1] += wa.w * v1; acc[3][2] += wa.w * v2; acc[3][3] += wa.w * v3;
            acc[4][0] += wb.x * v0; acc[4][1] += wb.x * v1; acc[4][2] += wb.x * v2; acc[4][3] += wb.x * v3;
            acc[5][0] += wb.y * v0; acc[5][1] += wb.y * v1; acc[5][2] += wb.y * v2; acc[5][3] += wb.y * v3;
            acc[6][0] += wb.z * v0; acc[6][1] += wb.z * v1; acc[6][2] += wb.z * v2; acc[6][3] += wb.z * v3;
            acc[7][0] += wb.w * v0; acc[7][1] += wb.w * v1; acc[7][2] += wb.w * v2; acc[7][3] += wb.w * v3;
        }
    }

    int gy = y0 + py;
#pragma unroll
    for (int mm = 0; mm < 8; mm++) {
        float bv = g_bias[b * 32 + m0 + mm];
        float* orow = out + ((size_t)(b * 32 + m0 + mm) * Hh + gy) * Ww + x0 + c;
#pragma unroll
        for (int j = 0; j < 4; j++) orow[4 * j] = acc[mm][j] + bv;
    }
}

// ---------------------------------------------------------------------------
extern "C" void kernel_launch(void* const* d_in, const int* in_sizes, int n_in,
                              void* d_out, int out_size) {
    const float* x   = (const float*)d_in[0];
    const float* a1w = (const float*)d_in[1];
    const float* a1b = (const float*)d_in[2];
    const float* a2w = (const float*)d_in[3];
    const float* a2b = (const float*)d_in[4];
    const float* a3w = (const float*)d_in[5];
    const float* a3b = (const float*)d_in[6];
    const float* b1w = (const float*)d_in[7];
    const float* b1b = (const float*)d_in[8];
    const float* b2w = (const float*)d_in[9];
    const float* b2b = (const float*)d_in[10];
    const float* wgt = (const float*)d_in[11];
    float* out = (float*)d_out;

    pooled_kernel<<<256, 256>>>(x);
    bias_kernel<<<1, 256>>>(b1w, b1b, b2w, b2b);

    int smA = (32 * 34 * AXS + 2592 + 81 + 81 + 9 + 9 + 9) * (int)sizeof(float);
    cudaFuncSetAttribute(attn_kernel, cudaFuncAttributeMaxDynamicSharedMemorySize, smA);
    attn_kernel<<<dim3(6, 6, 8), 256, smA>>>(x, a1w, a1b, a2w, a2b, a3w, a3b);

    int smM = (11520 + 9216 + 2304) * (int)sizeof(float);
    cudaFuncSetAttribute(main_kernel, cudaFuncAttributeMaxDynamicSharedMemorySize, smM);
    main_kernel<<<dim3(12, 12, 8), 256, smM>>>(x, wgt, out);
}

// round 2
// speedup vs baseline: 1.1434x; 1.1434x over previous
#include <cuda_runtime.h>

#define Hh 192
#define Ww 192

// Scratch (no cudaMalloc allowed)
__device__ float g_att[8 * 9 * 192 * 192];   // attention maps [b][p][y][x]
__device__ float g_pooled[8 * 32];
__device__ float g_bias[8 * 32];

// ---------------------------------------------------------------------------
// f32x2 packed helpers (sm_103a FFMA2 path)
// ---------------------------------------------------------------------------
__device__ __forceinline__ unsigned long long pk2(float lo, float hi) {
    unsigned long long r;
    asm("mov.b64 %0,{%1,%2};" : "=l"(r) : "f"(lo), "f"(hi));
    return r;
}
__device__ __forceinline__ void upk2(unsigned long long v, float& lo, float& hi) {
    asm("mov.b64 {%0,%1},%2;" : "=f"(lo), "=f"(hi) : "l"(v));
}
__device__ __forceinline__ unsigned long long fma2(unsigned long long a,
                                                   unsigned long long b,
                                                   unsigned long long c) {
    unsigned long long r;
    asm("fma.rn.f32x2 %0,%1,%2,%3;" : "=l"(r) : "l"(a), "l"(b), "l"(c));
    return r;
}
__device__ __forceinline__ unsigned long long mul2(unsigned long long a,
                                                   unsigned long long b) {
    unsigned long long r;
    asm("mul.rn.f32x2 %0,%1,%2;" : "=l"(r) : "l"(a), "l"(b));
    return r;
}

// ---------------------------------------------------------------------------
// Kernel 1: global average pool. One block per (b,n).
// ---------------------------------------------------------------------------
__global__ void pooled_kernel(const float* __restrict__ x) {
    int bn = blockIdx.x;  // 0..255
    const float* p = x + (size_t)bn * Hh * Ww;
    float s = 0.f;
    for (int i = threadIdx.x; i < Hh * Ww; i += 256) s += p[i];
    __shared__ float red[256];
    red[threadIdx.x] = s;
    __syncthreads();
    for (int o = 128; o > 0; o >>= 1) {
        if (threadIdx.x < o) red[threadIdx.x] += red[threadIdx.x + o];
        __syncthreads();
    }
    if (threadIdx.x == 0) g_pooled[bn] = red[0] * (1.f / (Hh * Ww));
}

// ---------------------------------------------------------------------------
// Kernel 2: bias MLP.
// ---------------------------------------------------------------------------
__global__ void bias_kernel(const float* __restrict__ b1w, const float* __restrict__ b1b,
                            const float* __restrict__ b2w, const float* __restrict__ b2b) {
    __shared__ float h[8 * 32];
    int t = threadIdx.x;
    int b = t >> 5, k = t & 31;
    float s = b1b[k];
    for (int n = 0; n < 32; n++) s += g_pooled[b * 32 + n] * b1w[k * 32 + n];
    h[t] = fmaxf(s, 0.f);
    __syncthreads();
    int m = k;
    float s2 = b2b[m];
    for (int kk = 0; kk < 32; kk++) s2 += h[b * 32 + kk] * b2w[m * 32 + kk];
    g_bias[t] = s2;
}

// ---------------------------------------------------------------------------
// Kernel 3: attention stack (unchanged from R1).
// ---------------------------------------------------------------------------
#define AXS 40
__global__ __launch_bounds__(256, 1)
void attn_kernel(const float* __restrict__ x, const float* __restrict__ a1w,
                 const float* __restrict__ a1b, const float* __restrict__ a2w,
                 const float* __restrict__ a2b, const float* __restrict__ a3w,
                 const float* __restrict__ a3b) {
    extern __shared__ float sm[];
    float* xs = sm;                     // 32*34*40
    float* w1 = xs + 32 * 34 * AXS;     // 2592  [o][n][t]
    float* w2 = w1 + 2592;              // 81
    float* w3 = w2 + 81;                // 81
    float* bb1 = w3 + 81;               // 9
    float* bb2 = bb1 + 9;               // 9
    float* bb3 = bb2 + 9;               // 9

    int b = blockIdx.z;
    int y0 = blockIdx.y * 32, x0 = blockIdx.x * 32;
    int tid = threadIdx.x;

    for (int i = tid; i < 2592; i += 256) w1[i] = a1w[i];
    if (tid < 81) { w2[tid] = a2w[tid]; w3[tid] = a3w[tid]; }
    if (tid < 9) { bb1[tid] = a1b[tid]; bb2[tid] = a2b[tid]; bb3[tid] = a3b[tid]; }

    const float* xb = x + (size_t)b * 32 * Hh * Ww;
    for (int i = tid; i < 32 * 34 * 34; i += 256) {
        int n = i / (34 * 34);
        int r = i % (34 * 34);
        int yy = r / 34, xx = r % 34;
        int gy = y0 + yy - 1, gx = x0 + xx - 1;
        float v = 0.f;
        if ((unsigned)gy < Hh && (unsigned)gx < Ww) v = xb[(n * Hh + gy) * Ww + gx];
        xs[(n * 34 + yy) * AXS + xx] = v;
    }
    __syncthreads();

    int py = tid >> 3;      // 0..31
    int c = tid & 7;        // 0..7, pixels px = c + 8*j

    float acc[9][4];
#pragma unroll
    for (int o = 0; o < 9; o++)
#pragma unroll
        for (int j = 0; j < 4; j++) acc[o][j] = 0.f;

    for (int n = 0; n < 32; n++) {
        const float* xr = xs + (n * 34 + py) * AXS + c;
        const float* wn = w1 + n * 9;
#pragma unroll
        for (int ki = 0; ki < 3; ki++) {
#pragma unroll
            for (int kj = 0; kj < 3; kj++) {
                float v0 = xr[ki * AXS + kj];
                float v1 = xr[ki * AXS + kj + 8];
                float v2 = xr[ki * AXS + kj + 16];
                float v3 = xr[ki * AXS + kj + 24];
                int t = ki * 3 + kj;
#pragma unroll
                for (int o = 0; o < 9; o++) {
                    float w = wn[o * 288 + t];
                    acc[o][0] += w * v0;
                    acc[o][1] += w * v1;
                    acc[o][2] += w * v2;
                    acc[o][3] += w * v3;
                }
            }
        }
    }

    int gy = y0 + py;
#pragma unroll
    for (int j = 0; j < 4; j++) {
        int gx = x0 + c + 8 * j;
        float u[9], z[9];
#pragma unroll
        for (int o = 0; o < 9; o++) u[o] = fmaxf(acc[o][j] + bb1[o], 0.f);
#pragma unroll
        for (int o2 = 0; o2 < 9; o2++) {
            float s = bb2[o2];
#pragma unroll
            for (int o = 0; o < 9; o++) s += w2[o2 * 9 + o] * u[o];
            z[o2] = fmaxf(s, 0.f);
        }
#pragma unroll
        for (int o3 = 0; o3 < 9; o3++) {
            float s = bb3[o3];
#pragma unroll
            for (int o2 = 0; o2 < 9; o2++) s += w3[o3 * 9 + o2] * z[o2];
            float att = 1.f / (1.f + __expf(-s));
            g_att[((b * 9 + o3) * Hh + gy) * Ww + gx] = att;
        }
    }
}

// ---------------------------------------------------------------------------
// Kernel 4: main attention-weighted conv — f32x2 packed over channel pairs.
// Tile 16x16 pixels, 256 threads = 4 m-groups x 64 pixel-groups.
// Thread: 8 m x 4 px, acc = f32x2 (even/odd channel partial sums).
// xs interleaved: [n2][yy][xp][e] (e = n&1) -> one LDS.64 = {x_even, x_odd}.
// ws interleaved: [p][n2][m][e]            -> one LDS.64 broadcast = matching w pair.
// ---------------------------------------------------------------------------
#define MXP 20
__global__ __launch_bounds__(256, 2)
void main_kernel(const float* __restrict__ x, const float* __restrict__ weight,
                 float* __restrict__ out) {
    extern __shared__ float sm[];
    float* xs = sm;                 // 16*18*20*2 = 11520
    float* ws = xs + 11520;         // 9*16*32*2  = 9216  [p][n2][m][e]
    float* atts = ws + 9216;        // 9*16*16    = 2304

    int b = blockIdx.z;
    int y0 = blockIdx.y * 16, x0 = blockIdx.x * 16;
    int tid = threadIdx.x;

    const float* xb = x + (size_t)b * 32 * Hh * Ww;
    for (int i = tid; i < 32 * 18 * 18; i += 256) {
        int n = i / (18 * 18);
        int r = i % (18 * 18);
        int yy = r / 18, xx = r % 18;
        int gy = y0 + yy - 1, gx = x0 + xx - 1;
        float v = 0.f;
        if ((unsigned)gy < Hh && (unsigned)gx < Ww) v = xb[(n * Hh + gy) * Ww + gx];
        xs[(((n >> 1) * 18 + yy) * MXP + xx) * 2 + (n & 1)] = v;
    }
    for (int i = tid; i < 9216; i += 256) {
        int q = i >> 2;         // float4 group
        int c4 = i & 3;
        int p = q >> 8;
        int n2 = (q >> 4) & 15;
        int m2 = q & 15;
        int m = 2 * m2 + (c4 >> 1);
        int n = 2 * n2 + (c4 & 1);
        ws[i] = weight[(m * 32 + n) * 9 + p];
    }
    for (int i = tid; i < 2304; i += 256) {
        int p = i >> 8;
        int r = i & 255;
        int yy = r >> 4, xx = r & 15;
        atts[i] = g_att[((b * 9 + p) * Hh + y0 + yy) * Ww + x0 + xx];
    }
    __syncthreads();

    int mg = tid >> 6;        // 0..3
    int pg = tid & 63;
    int m0 = mg * 8;
    int py = pg >> 2;         // 0..15
    int c = pg & 3;           // pixels px = c + 4*j

    const unsigned long long* xs64 = (const unsigned long long*)xs;   // [n2*360 + yy*20 + xx]
    const unsigned long long* ws64 = (const unsigned long long*)ws;   // [(p*16+n2)*32 + m]

    unsigned long long acc[8][4];
#pragma unroll
    for (int mm = 0; mm < 8; mm++)
#pragma unroll
        for (int j = 0; j < 4; j++) acc[mm][j] = 0ull;

#pragma unroll
    for (int p = 0; p < 9; p++) {
        int ki = p / 3, kj = p % 3;
        unsigned long long att2[4];
#pragma unroll
        for (int j = 0; j < 4; j++) {
            float a = atts[(p * 16 + py) * 16 + c + 4 * j];
            att2[j] = pk2(a, a);
        }
        const unsigned long long* wp = ws64 + p * 512 + m0;
        int xbase = (py + ki) * MXP + c + kj;
#pragma unroll 4
        for (int n2 = 0; n2 < 16; n2++) {
            const unsigned long long* xr = xs64 + n2 * 360 + xbase;
            unsigned long long v0 = mul2(xr[0],  att2[0]);
            unsigned long long v1 = mul2(xr[4],  att2[1]);
            unsigned long long v2 = mul2(xr[8],  att2[2]);
            unsigned long long v3 = mul2(xr[12], att2[3]);
            const unsigned long long* wr = wp + n2 * 32;
#pragma unroll
            for (int mm = 0; mm < 8; mm++) {
                unsigned long long w = wr[mm];
                acc[mm][0] = fma2(w, v0, acc[mm][0]);
                acc[mm][1] = fma2(w, v1, acc[mm][1]);
                acc[mm][2] = fma2(w, v2, acc[mm][2]);
                acc[mm][3] = fma2(w, v3, acc[mm][3]);
            }
        }
    }

    int gy = y0 + py;
#pragma unroll
    for (int mm = 0; mm < 8; mm++) {
        float bv = g_bias[b * 32 + m0 + mm];
        float* orow = out + ((size_t)(b * 32 + m0 + mm) * Hh + gy) * Ww + x0 + c;
#pragma unroll
        for (int j = 0; j < 4; j++) {
            float lo, hi;
            upk2(acc[mm][j], lo, hi);
            orow[4 * j] = lo + hi + bv;
        }
    }
}

// ---------------------------------------------------------------------------
extern "C" void kernel_launch(void* const* d_in, const int* in_sizes, int n_in,
                              void* d_out, int out_size) {
    const float* x   = (const float*)d_in[0];
    const float* a1w = (const float*)d_in[1];
    const float* a1b = (const float*)d_in[2];
    const float* a2w = (const float*)d_in[3];
    const float* a2b = (const float*)d_in[4];
    const float* a3w = (const float*)d_in[5];
    const float* a3b = (const float*)d_in[6];
    const float* b1w = (const float*)d_in[7];
    const float* b1b = (const float*)d_in[8];
    const float* b2w = (const float*)d_in[9];
    const float* b2b = (const float*)d_in[10];
    const float* wgt = (const float*)d_in[11];
    float* out = (float*)d_out;

    pooled_kernel<<<256, 256>>>(x);
    bias_kernel<<<1, 256>>>(b1w, b1b, b2w, b2b);

    int smA = (32 * 34 * AXS + 2592 + 81 + 81 + 9 + 9 + 9) * (int)sizeof(float);
    cudaFuncSetAttribute(attn_kernel, cudaFuncAttributeMaxDynamicSharedMemorySize, smA);
    attn_kernel<<<dim3(6, 6, 8), 256, smA>>>(x, a1w, a1b, a2w, a2b, a3w, a3b);

    int smM = (11520 + 9216 + 2304) * (int)sizeof(float);
    cudaFuncSetAttribute(main_kernel, cudaFuncAttributeMaxDynamicSharedMemorySize, smM);
    main_kernel<<<dim3(12, 12, 8), 256, smM>>>(x, wgt, out);
}

// round 3
// speedup vs baseline: 1.1995x; 1.0491x over previous
#include <cuda_runtime.h>

#define Hh 192
#define Ww 192

__device__ float g_att[8 * 9 * 192 * 192];   // [b][p][y][x]
__device__ float g_pooled[8 * 32];
__device__ float g_bias[8 * 32];

typedef unsigned long long ull;

__device__ __forceinline__ ull pk2(float lo, float hi) {
    ull r; asm("mov.b64 %0,{%1,%2};" : "=l"(r) : "f"(lo), "f"(hi)); return r;
}
__device__ __forceinline__ void upk2(ull v, float& lo, float& hi) {
    asm("mov.b64 {%0,%1},%2;" : "=f"(lo), "=f"(hi) : "l"(v));
}
__device__ __forceinline__ ull fma2(ull a, ull b, ull c) {
    ull r; asm("fma.rn.f32x2 %0,%1,%2,%3;" : "=l"(r) : "l"(a), "l"(b), "l"(c)); return r;
}
__device__ __forceinline__ ull mul2(ull a, ull b) {
    ull r; asm("mul.rn.f32x2 %0,%1,%2;" : "=l"(r) : "l"(a), "l"(b)); return r;
}

// ---------------------------------------------------------------------------
// Kernel 1: global average pool.
// ---------------------------------------------------------------------------
__global__ void pooled_kernel(const float* __restrict__ x) {
    int bn = blockIdx.x;
    const float* p = x + (size_t)bn * Hh * Ww;
    float s = 0.f;
    for (int i = threadIdx.x; i < Hh * Ww; i += 256) s += p[i];
    __shared__ float red[256];
    red[threadIdx.x] = s;
    __syncthreads();
    for (int o = 128; o > 0; o >>= 1) {
        if (threadIdx.x < o) red[threadIdx.x] += red[threadIdx.x + o];
        __syncthreads();
    }
    if (threadIdx.x == 0) g_pooled[bn] = red[0] * (1.f / (Hh * Ww));
}

// ---------------------------------------------------------------------------
// Kernel 2: bias MLP.
// ---------------------------------------------------------------------------
__global__ void bias_kernel(const float* __restrict__ b1w, const float* __restrict__ b1b,
                            const float* __restrict__ b2w, const float* __restrict__ b2b) {
    __shared__ float h[8 * 32];
    int t = threadIdx.x;
    int b = t >> 5, k = t & 31;
    float s = b1b[k];
    for (int n = 0; n < 32; n++) s += g_pooled[b * 32 + n] * b1w[k * 32 + n];
    h[t] = fmaxf(s, 0.f);
    __syncthreads();
    int m = k;
    float s2 = b2b[m];
    for (int kk = 0; kk < 32; kk++) s2 += h[b * 32 + kk] * b2w[m * 32 + kk];
    g_bias[t] = s2;
}

// ---------------------------------------------------------------------------
// Kernel 3: attention stack — f32x2 packed over output-channel pairs.
// Tile 16x32 px, 256 threads, 2 px/thread (c, c+16), smem ~104KB -> 2 CTA/SM.
// w1 re-laid [n][t][o] padded o->10 so {o,o+1} is one aligned broadcast LDS.64.
// Warp row mapping: warp w covers rows {base, base+2} (delta 2 rows = bank
// offset 16 with stride 40) -> conflict-free x loads.
// ---------------------------------------------------------------------------
#define AXS 40
__global__ __launch_bounds__(256, 2)
void attn_kernel(const float* __restrict__ x, const float* __restrict__ a1w,
                 const float* __restrict__ a1b, const float* __restrict__ a2w,
                 const float* __restrict__ a2b, const float* __restrict__ a3w,
                 const float* __restrict__ a3b) {
    extern __shared__ float sm[];
    float* xs = sm;                  // 32*18*40 = 23040
    float* w1p = xs + 23040;         // 32*9*10 = 2880  [n][t][o(pad10)]
    float* w2 = w1p + 2880;          // 81
    float* w3 = w2 + 81;             // 81
    float* bb1 = w3 + 81;            // 9
    float* bb2 = bb1 + 9;            // 9
    float* bb3 = bb2 + 9;            // 9

    int b = blockIdx.z;
    int y0 = blockIdx.y * 16, x0 = blockIdx.x * 32;
    int tid = threadIdx.x;

    for (int i = tid; i < 2880; i += 256) {
        int nt = i / 10, o = i % 10;
        w1p[i] = (o < 9) ? a1w[o * 288 + nt] : 0.f;
    }
    if (tid < 81) { w2[tid] = a2w[tid]; w3[tid] = a3w[tid]; }
    if (tid < 9) { bb1[tid] = a1b[tid]; bb2[tid] = a2b[tid]; bb3[tid] = a3b[tid]; }

    const float* xb = x + (size_t)b * 32 * Hh * Ww;
    for (int i = tid; i < 32 * 18 * 34; i += 256) {
        int n = i / (18 * 34);
        int r = i % (18 * 34);
        int yy = r / 34, xx = r % 34;
        int gy = y0 + yy - 1, gx = x0 + xx - 1;
        float v = 0.f;
        if ((unsigned)gy < Hh && (unsigned)gx < Ww) v = xb[(n * Hh + gy) * Ww + gx];
        xs[(n * 18 + yy) * AXS + xx] = v;
    }
    __syncthreads();

    int w = tid >> 5;                 // warp 0..7
    int half = (tid >> 4) & 1;        // half-warp
    int c = tid & 15;
    int py = (w & 1) + (w >> 1) * 4 + 2 * half;   // rows: pairs delta=2 per warp

    ull acc[2][5];
#pragma unroll
    for (int j = 0; j < 2; j++)
#pragma unroll
        for (int q = 0; q < 5; q++) acc[j][q] = 0ull;

    for (int n = 0; n < 32; n++) {
        const float* xr = xs + (n * 18 + py) * AXS + c;
        const ull* wn = (const ull*)(w1p + n * 90);
#pragma unroll
        for (int t = 0; t < 9; t++) {
            const int ki = t / 3, kj = t % 3;
            float v0 = xr[ki * AXS + kj];
            float v1 = xr[ki * AXS + kj + 16];
            ull A = pk2(v0, v0);
            ull B = pk2(v1, v1);
            const ull* wt = wn + t * 5;
#pragma unroll
            for (int q = 0; q < 5; q++) {
                ull W = wt[q];
                acc[0][q] = fma2(W, A, acc[0][q]);
                acc[1][q] = fma2(W, B, acc[1][q]);
            }
        }
    }

    int gy = y0 + py;
#pragma unroll
    for (int j = 0; j < 2; j++) {
        int gx = x0 + c + 16 * j;
        float u[9], z[9], dummy;
#pragma unroll
        for (int q = 0; q < 4; q++) upk2(acc[j][q], u[2 * q], u[2 * q + 1]);
        upk2(acc[j][4], u[8], dummy);
#pragma unroll
        for (int o = 0; o < 9; o++) u[o] = fmaxf(u[o] + bb1[o], 0.f);
#pragma unroll
        for (int o2 = 0; o2 < 9; o2++) {
            float s = bb2[o2];
#pragma unroll
            for (int o = 0; o < 9; o++) s += w2[o2 * 9 + o] * u[o];
            z[o2] = fmaxf(s, 0.f);
        }
#pragma unroll
        for (int o3 = 0; o3 < 9; o3++) {
            float s = bb3[o3];
#pragma unroll
            for (int o2 = 0; o2 < 9; o2++) s += w3[o3 * 9 + o2] * z[o2];
            float att = 1.f / (1.f + __expf(-s));
            g_att[((b * 9 + o3) * Hh + gy) * Ww + gx] = att;
        }
    }
}

// ---------------------------------------------------------------------------
// Kernel 4: main conv — f32x2 channel pairs; weights via LDS.128 (2 m/load).
// ---------------------------------------------------------------------------
#define MXP 20
__global__ __launch_bounds__(256, 2)
void main_kernel(const float* __restrict__ x, const float* __restrict__ weight,
                 float* __restrict__ out) {
    extern __shared__ float sm[];
    float* xs = sm;                 // 16*18*20*2 = 11520
    float* ws = xs + 11520;         // 9*16*32*2  = 9216  [p][n2][m][e]
    float* atts = ws + 9216;        // 2304

    int b = blockIdx.z;
    int y0 = blockIdx.y * 16, x0 = blockIdx.x * 16;
    int tid = threadIdx.x;

    const float* xb = x + (size_t)b * 32 * Hh * Ww;
    for (int i = tid; i < 32 * 18 * 18; i += 256) {
        int n = i / (18 * 18);
        int r = i % (18 * 18);
        int yy = r / 18, xx = r % 18;
        int gy = y0 + yy - 1, gx = x0 + xx - 1;
        float v = 0.f;
        if ((unsigned)gy < Hh && (unsigned)gx < Ww) v = xb[(n * Hh + gy) * Ww + gx];
        xs[(((n >> 1) * 18 + yy) * MXP + xx) * 2 + (n & 1)] = v;
    }
    for (int i = tid; i < 9216; i += 256) {
        int q = i >> 2;
        int c4 = i & 3;
        int p = q >> 8;
        int n2 = (q >> 4) & 15;
        int m2 = q & 15;
        int m = 2 * m2 + (c4 >> 1);
        int n = 2 * n2 + (c4 & 1);
        ws[i] = weight[(m * 32 + n) * 9 + p];
    }
    for (int i = tid; i < 2304; i += 256) {
        int p = i >> 8;
        int r = i & 255;
        int yy = r >> 4, xx = r & 15;
        atts[i] = g_att[((b * 9 + p) * Hh + y0 + yy) * Ww + x0 + xx];
    }
    __syncthreads();

    int mg = tid >> 6;
    int pg = tid & 63;
    int m0 = mg * 8;
    int py = pg >> 2;
    int c = pg & 3;

    const ull* xs64 = (const ull*)xs;   // [n2*360 + yy*20 + xx]
    const ull* ws64 = (const ull*)ws;   // [(p*16+n2)*32 + m]

    ull acc[8][4];
#pragma unroll
    for (int mm = 0; mm < 8; mm++)
#pragma unroll
        for (int j = 0; j < 4; j++) acc[mm][j] = 0ull;

#pragma unroll
    for (int p = 0; p < 9; p++) {
        int ki = p / 3, kj = p % 3;
        ull att2[4];
#pragma unroll
        for (int j = 0; j < 4; j++) {
            float a = atts[(p * 16 + py) * 16 + c + 4 * j];
            att2[j] = pk2(a, a);
        }
        const ull* wp = ws64 + p * 512 + m0;
        int xbase = (py + ki) * MXP + c + kj;
#pragma unroll 4
        for (int n2 = 0; n2 < 16; n2++) {
            const ull* xr = xs64 + n2 * 360 + xbase;
            ull v0 = mul2(xr[0],  att2[0]);
            ull v1 = mul2(xr[4],  att2[1]);
            ull v2 = mul2(xr[8],  att2[2]);
            ull v3 = mul2(xr[12], att2[3]);
            const ulonglong2* wr2 = (const ulonglong2*)(wp + n2 * 32);
            ulonglong2 w01 = wr2[0];
            ulonglong2 w23 = wr2[1];
            ulonglong2 w45 = wr2[2];
            ulonglong2 w67 = wr2[3];
            acc[0][0] = fma2(w01.x, v0, acc[0][0]); acc[0][1] = fma2(w01.x, v1, acc[0][1]);
            acc[0][2] = fma2(w01.x, v2, acc[0][2]); acc[0][3] = fma2(w01.x, v3, acc[0][3]);
            acc[1][0] = fma2(w01.y, v0, acc[1][0]); acc[1][1] = fma2(w01.y, v1, acc[1][1]);
            acc[1][2] = fma2(w01.y, v2, acc[1][2]); acc[1][3] = fma2(w01.y, v3, acc[1][3]);
            acc[2][0] = fma2(w23.x, v0, acc[2][0]); acc[2][1] = fma2(w23.x, v1, acc[2][1]);
            acc[2][2] = fma2(w23.x, v2, acc[2][2]); acc[2][3] = fma2(w23.x, v3, acc[2][3]);
            acc[3][0] = fma2(w23.y, v0, acc[3][0]); acc[3][1] = fma2(w23.y, v1, acc[3][1]);
            acc[3][2] = fma2(w23.y, v2, acc[3][2]); acc[3][3] = fma2(w23.y, v3, acc[3][3]);
            acc[4][0] = fma2(w45.x, v0, acc[4][0]); acc[4][1] = fma2(w45.x, v1, acc[4][1]);
            acc[4][2] = fma2(w45.x, v2, acc[4][2]); acc[4][3] = fma2(w45.x, v3, acc[4][3]);
            acc[5][0] = fma2(w45.y, v0, acc[5][0]); acc[5][1] = fma2(w45.y, v1, acc[5][1]);
            acc[5][2] = fma2(w45.y, v2, acc[5][2]); acc[5][3] = fma2(w45.y, v3, acc[5][3]);
            acc[6][0] = fma2(w67.x, v0, acc[6][0]); acc[6][1] = fma2(w67.x, v1, acc[6][1]);
            acc[6][2] = fma2(w67.x, v2, acc[6][2]); acc[6][3] = fma2(w67.x, v3, acc[6][3]);
            acc[7][0] = fma2(w67.y, v0, acc[7][0]); acc[7][1] = fma2(w67.y, v1, acc[7][1]);
            acc[7][2] = fma2(w67.y, v2, acc[7][2]); acc[7][3] = fma2(w67.y, v3, acc[7][3]);
        }
    }

    int gy = y0 + py;
#pragma unroll
    for (int mm = 0; mm < 8; mm++) {
        float bv = g_bias[b * 32 + m0 + mm];
        float* orow = out + ((size_t)(b * 32 + m0 + mm) * Hh + gy) * Ww + x0 + c;
#pragma unroll
        for (int j = 0; j < 4; j++) {
            float lo, hi;
            upk2(acc[mm][j], lo, hi);
            orow[4 * j] = lo + hi + bv;
        }
    }
}

// ---------------------------------------------------------------------------
extern "C" void kernel_launch(void* const* d_in, const int* in_sizes, int n_in,
                              void* d_out, int out_size) {
    const float* x   = (const float*)d_in[0];
    const float* a1w = (const float*)d_in[1];
    const float* a1b = (const float*)d_in[2];
    const float* a2w = (const float*)d_in[3];
    const float* a2b = (const float*)d_in[4];
    const float* a3w = (const float*)d_in[5];
    const float* a3b = (const float*)d_in[6];
    const float* b1w = (const float*)d_in[7];
    const float* b1b = (const float*)d_in[8];
    const float* b2w = (const float*)d_in[9];
    const float* b2b = (const float*)d_in[10];
    const float* wgt = (const float*)d_in[11];
    float* out = (float*)d_out;

    pooled_kernel<<<256, 256>>>(x);
    bias_kernel<<<1, 256>>>(b1w, b1b, b2w, b2b);

    int smA = (23040 + 2880 + 81 + 81 + 9 + 9 + 9) * (int)sizeof(float);
    cudaFuncSetAttribute(attn_kernel, cudaFuncAttributeMaxDynamicSharedMemorySize, smA);
    attn_kernel<<<dim3(6, 12, 8), 256, smA>>>(x, a1w, a1b, a2w, a2b, a3w, a3b);

    int smM = (11520 + 9216 + 2304) * (int)sizeof(float);
    cudaFuncSetAttribute(main_kernel, cudaFuncAttributeMaxDynamicSharedMemorySize, smM);
    main_kernel<<<dim3(12, 12, 8), 256, smM>>>(x, wgt, out);
}